// round 16
// baseline (speedup 1.0000x reference)
#include <cuda_runtime.h>
#include <stdint.h>

// Fused projection + greedy per-pixel NMS. Output dtype is FLOAT32.
//   coords_grid: [N, M, 3, H, W] f32,  anchor_P: [N, 3, 4] f32
//   out: [N, H, W, 8] f32 (indices as floats)
//
// R16: shape-specialized (HW, M compile-time) on top of R15's single-wave
// config (32 regs, 8 CTA/SM). Fully-unrolled vote-free prefix m=1..11 with
// immediate-offset LDGs (no pointer math, no stage-rotate MOVs, no votes),
// then the voted pipelined loop, then the no-load epilogue.
#define TOPK 8

__device__ __forceinline__ float fast_rcp(float z) {
    float r;
    asm("rcp.approx.ftz.f32 %0, %1;" : "=f"(r) : "f"(z));
    return r;
}

#define PROJECT(cx, cy, cz, X, Y)                                             \
  do {                                                                        \
    const float X0 = fmaf(p00, (cx), fmaf(p01, (cy), fmaf(p02, (cz), p03)));  \
    const float X1 = fmaf(p10, (cx), fmaf(p11, (cy), fmaf(p12, (cz), p13)));  \
    const float X2 = fmaf(p20, (cx), fmaf(p21, (cy), fmaf(p22, (cz), p23)));  \
    const float zc = fmaxf(X2, 1e-6f);                                        \
    const float iv = fast_rcp(zc);                                            \
    (X) = X0 * iv;                                                            \
    (Y) = X1 * iv;                                                            \
  } while (0)

// Suppress/insert candidate MVAL whose projection is (x1,y1); all 8 slots.
#define SUPPRESS_INSERT(MVAL)                                                 \
  do {                                                                        \
    float d2_[TOPK];                                                          \
    _Pragma("unroll")                                                         \
    for (int k = 0; k < TOPK; k++) {                                          \
      const float dx = sx[k] - x1;                                            \
      const float dy = sy[k] - y1;                                            \
      d2_[k] = fmaf(dx, dx, dy * dy);                                         \
    }                                                                         \
    const float dmn = fminf(fminf(fminf(d2_[0], d2_[1]), fminf(d2_[2], d2_[3])), \
                            fminf(fminf(d2_[4], d2_[5]), fminf(d2_[6], d2_[7]))); \
    if ((dmn > 4.0f) && (cnt < TOPK)) {                                       \
      _Pragma("unroll")                                                       \
      for (int k = 1; k < TOPK; k++) {                                        \
        if (cnt == k) { sx[k] = x1; sy[k] = y1; }                             \
      }                                                                       \
      si64 |= (uint64_t)(uint32_t)(MVAL) << (cnt * 8);                        \
      cnt++;                                                                  \
    }                                                                         \
  } while (0)

// ============================ specialized kernel ============================
// HW_C % 256 == 0, M_C in [14, 255]. All strides compile-time; prefix loads
// are immediate-offset LDGs from `base`.
template <int HW_C, int M_C, bool VEC_STORE>
__global__ __launch_bounds__(256, 8)
void nms_coords_spec(const float* __restrict__ coords,
                     const float* __restrict__ P,
                     float* __restrict__ out)
{
    constexpr long long plane   = HW_C;
    constexpr long long mstride = 3LL * HW_C;

    const int bpix = blockIdx.x * 256;
    const int n    = bpix / HW_C;                 // const-div -> mul/shift
    const int pix  = bpix - n * HW_C + threadIdx.x;

    const float* Pn = P + n * 12;
    const float p00 = Pn[0], p01 = Pn[1], p02 = Pn[2],  p03 = Pn[3];
    const float p10 = Pn[4], p11 = Pn[5], p12 = Pn[6],  p13 = Pn[7];
    const float p20 = Pn[8], p21 = Pn[9], p22 = Pn[10], p23 = Pn[11];

    const float* base = coords + (long long)n * M_C * mstride + pix;

    float sx[TOPK], sy[TOPK];
#pragma unroll
    for (int k = 0; k < TOPK; k++) { sx[k] = 1e9f; sy[k] = 1e9f; }
    uint64_t si64 = 0;

    // m = 0: always kept; index byte stays 0.
    {
        const float cx = base[0];
        const float cy = base[plane];
        const float cz = base[2 * plane];
        PROJECT(cx, cy, cz, sx[0], sy[0]);
    }
    int cnt = 1;

    // Prime: x1,y1 = proj(1); held coords = coords[2] (all imm offsets).
    float x1, y1;
    {
        const float cx = base[mstride];
        const float cy = base[mstride + plane];
        const float cz = base[mstride + 2 * plane];
        PROJECT(cx, cy, cz, x1, y1);
    }
    float cx1 = base[2 * mstride];
    float cy1 = base[2 * mstride + plane];
    float cz1 = base[2 * mstride + 2 * plane];

    // Fully-unrolled vote-free prefix m = 1..11 (M_C >= 14 so loads of m+2
    // <= 13 <= M_C-1 are in-bounds). Renaming removes all rotate MOVs; loads
    // are LDG [base + imm].
    constexpr int PREFIX_END = 11;      // last m handled in the prefix
#pragma unroll
    for (int m = 1; m <= PREFIX_END; m++) {
        const long long off = (long long)(m + 2) * mstride;   // compile-time
        const float nx = base[off];
        const float ny = base[off + plane];
        const float nz = base[off + 2 * plane];
        float x2, y2;
        PROJECT(cx1, cy1, cz1, x2, y2);
        SUPPRESS_INSERT(m);
        x1 = x2; y1 = y2;
        cx1 = nx; cy1 = ny; cz1 = nz;
    }
    // State now: x1 = proj(12), held coords = coords[13].

    // Voted pipelined region: m = 12 .. M_C-3 (prefetch m+2 <= M_C-1).
    const float* pf = base + (long long)(PREFIX_END + 3) * mstride;  // m=14
    bool alldone = false;
    for (int m = PREFIX_END + 1; m <= M_C - 3; m++) {
        const float nx = pf[0];
        const float ny = pf[plane];
        const float nz = pf[2 * plane];
        float x2, y2;
        PROJECT(cx1, cy1, cz1, x2, y2);
        SUPPRESS_INSERT(m);
        x1 = x2; y1 = y2;
        cx1 = nx; cy1 = ny; cz1 = nz;
        pf += mstride;
        if (__all_sync(0xffffffffu, cnt >= TOPK)) { alldone = true; break; }
    }

    // No-load epilogue m = M_C-2, M_C-1 (skipped if early exit fired).
    if (!alldone) {
        {
            float x2, y2;
            PROJECT(cx1, cy1, cz1, x2, y2);
            SUPPRESS_INSERT(M_C - 2);
            x1 = x2; y1 = y2;
        }
        SUPPRESS_INSERT(M_C - 1);
    }

    const uint32_t lo = (uint32_t)si64;
    const uint32_t hi = (uint32_t)(si64 >> 32);
    const float f0 = (float)( lo        & 0xff);
    const float f1 = (float)((lo >>  8) & 0xff);
    const float f2 = (float)((lo >> 16) & 0xff);
    const float f3 = (float)((lo >> 24)       );
    const float f4 = (float)( hi        & 0xff);
    const float f5 = (float)((hi >>  8) & 0xff);
    const float f6 = (float)((hi >> 16) & 0xff);
    const float f7 = (float)((hi >> 24)       );

    const long long opix = (long long)n * HW_C + pix;
    if (VEC_STORE) {
        float4* o = reinterpret_cast<float4*>(out) + opix * 2;
        o[0] = make_float4(f0, f1, f2, f3);
        o[1] = make_float4(f4, f5, f6, f7);
    } else {
        float* o = out + opix * TOPK;
        o[0]=f0; o[1]=f1; o[2]=f2; o[3]=f3; o[4]=f4; o[5]=f5; o[6]=f6; o[7]=f7;
    }
}

// ===================== runtime fast kernel (R15, proven) ====================
#define CAND_BODY_RT(MVAL)                                                    \
  do {                                                                        \
    const float nx = pf[0];                                                   \
    const float ny = pf[plane];                                               \
    const float nz = pf[2 * plane];                                           \
    float x2, y2;                                                             \
    PROJECT(cx1, cy1, cz1, x2, y2);                                           \
    SUPPRESS_INSERT(MVAL);                                                    \
    x1 = x2; y1 = y2;                                                         \
    cx1 = nx; cy1 = ny; cz1 = nz;                                             \
    pf += mstride;                                                            \
  } while (0)

template <bool VEC_STORE>
__global__ __launch_bounds__(256, 8)
void nms_coords_fast(const float* __restrict__ coords,
                     const float* __restrict__ P,
                     float* __restrict__ out,
                     int HW, int M)
{
    const int bpix = blockIdx.x * 256;
    const int n    = bpix / HW;
    const int pix  = bpix - n * HW + threadIdx.x;

    const float* Pn = P + n * 12;
    const float p00 = Pn[0], p01 = Pn[1], p02 = Pn[2],  p03 = Pn[3];
    const float p10 = Pn[4], p11 = Pn[5], p12 = Pn[6],  p13 = Pn[7];
    const float p20 = Pn[8], p21 = Pn[9], p22 = Pn[10], p23 = Pn[11];

    const long long plane   = HW;
    const long long mstride = 3 * plane;
    const float* base = coords + (long long)n * M * mstride + pix;

    float sx[TOPK], sy[TOPK];
#pragma unroll
    for (int k = 0; k < TOPK; k++) { sx[k] = 1e9f; sy[k] = 1e9f; }
    uint64_t si64 = 0;

    {
        const float cx = base[0];
        const float cy = base[plane];
        const float cz = base[2 * plane];
        PROJECT(cx, cy, cz, sx[0], sy[0]);
    }
    int cnt = 1;

    float x1, y1;
    {
        const float* s1 = base + mstride;
        const float cx = s1[0], cy = s1[plane], cz = s1[2 * plane];
        PROJECT(cx, cy, cz, x1, y1);
    }
    float cx1, cy1, cz1;
    {
        const float* s2 = base + 2 * mstride;
        cx1 = s2[0]; cy1 = s2[plane]; cz1 = s2[2 * plane];
    }
    const float* pf = base + 3 * mstride;

#pragma unroll
    for (int m = 1; m < TOPK; m++) { CAND_BODY_RT(m); }

    bool alldone = false;
    for (int m = TOPK; m <= M - 3; m++) {
        CAND_BODY_RT(m);
        if (__all_sync(0xffffffffu, cnt >= TOPK)) { alldone = true; break; }
    }
    if (!alldone) {
        {
            float x2, y2;
            PROJECT(cx1, cy1, cz1, x2, y2);
            SUPPRESS_INSERT(M - 2);
            x1 = x2; y1 = y2;
        }
        SUPPRESS_INSERT(M - 1);
    }

    const uint32_t lo = (uint32_t)si64;
    const uint32_t hi = (uint32_t)(si64 >> 32);
    const float f0 = (float)( lo        & 0xff);
    const float f1 = (float)((lo >>  8) & 0xff);
    const float f2 = (float)((lo >> 16) & 0xff);
    const float f3 = (float)((lo >> 24)       );
    const float f4 = (float)( hi        & 0xff);
    const float f5 = (float)((hi >>  8) & 0xff);
    const float f6 = (float)((hi >> 16) & 0xff);
    const float f7 = (float)((hi >> 24)       );

    const long long opix = (long long)n * HW + pix;
    if (VEC_STORE) {
        float4* o = reinterpret_cast<float4*>(out) + opix * 2;
        o[0] = make_float4(f0, f1, f2, f3);
        o[1] = make_float4(f4, f5, f6, f7);
    } else {
        float* o = out + opix * TOPK;
        o[0]=f0; o[1]=f1; o[2]=f2; o[3]=f3; o[4]=f4; o[5]=f5; o[6]=f6; o[7]=f7;
    }
}

// ============================ generic fallback ==============================
__global__ __launch_bounds__(256)
void nms_coords_kernel_generic(const float* __restrict__ coords,
                               const float* __restrict__ P,
                               float* __restrict__ out,
                               int HW, int M, int total)
{
    const int tid = blockIdx.x * 256 + threadIdx.x;
    if (tid >= total) return;
    const int n   = tid / HW;
    const int pix = tid - n * HW;
    const float* Pn = P + n * 12;
    const float p00 = Pn[0], p01 = Pn[1], p02 = Pn[2],  p03 = Pn[3];
    const float p10 = Pn[4], p11 = Pn[5], p12 = Pn[6],  p13 = Pn[7];
    const float p20 = Pn[8], p21 = Pn[9], p22 = Pn[10], p23 = Pn[11];
    const long long plane = HW, mstride = 3 * plane;
    const float* cm = coords + (long long)n * M * mstride + pix;

    float sx[TOPK], sy[TOPK]; int si[TOPK];
#pragma unroll
    for (int k = 0; k < TOPK; k++) { sx[k] = 1e9f; sy[k] = 1e9f; si[k] = 0; }
    int cnt = 0;
    for (int m = 0; m < M; m++, cm += mstride) {
        const float cx = cm[0], cy = cm[plane], cz = cm[2 * plane];
        const float X0 = fmaf(p00, cx, fmaf(p01, cy, fmaf(p02, cz, p03)));
        const float X1 = fmaf(p10, cx, fmaf(p11, cy, fmaf(p12, cz, p13)));
        const float X2 = fmaf(p20, cx, fmaf(p21, cy, fmaf(p22, cz, p23)));
        const float zc = fmaxf(X2, 1e-6f);
        const float x = X0 / zc, y = X1 / zc;
        float dmin = 3.402823e38f;
#pragma unroll
        for (int k = 0; k < TOPK; k++) {
            const float dx = sx[k] - x, dy = sy[k] - y;
            dmin = fminf(dmin, fmaf(dx, dx, dy * dy));
        }
        if (dmin > 4.0f && cnt < TOPK) {
#pragma unroll
            for (int k = 0; k < TOPK; k++)
                if (cnt == k) { sx[k] = x; sy[k] = y; si[k] = m; }
            cnt++;
        }
    }
    float* o = out + (long long)tid * TOPK;
#pragma unroll
    for (int k = 0; k < TOPK; k++) o[k] = (float)si[k];
}

extern "C" void kernel_launch(void* const* d_in, const int* in_sizes, int n_in,
                              void* d_out, int out_size)
{
    int ci = 0, pi = 0;
    for (int i = 1; i < n_in; i++) {
        if (in_sizes[i] > in_sizes[ci]) ci = i;
        if (in_sizes[i] < in_sizes[pi]) pi = i;
    }
    const float* coords = (const float*)d_in[ci];
    const float* P      = (const float*)d_in[pi];
    float* out          = (float*)d_out;

    const long long p_elems      = in_sizes[pi];
    const long long coords_elems = in_sizes[ci];
    const int N  = (int)(p_elems / 12);
    const int HW = (int)(out_size / (TOPK * (long long)N));
    const int M  = (int)(coords_elems / (3LL * N * HW));
    const int total = N * HW;

    const bool aligned16 = ((((uintptr_t)d_out) & 15u) == 0);

    if (HW == 19200 && M == 32) {                      // this dataset instance
        const int blocks = total / 256;
        if (aligned16)
            nms_coords_spec<19200, 32, true><<<blocks, 256>>>(coords, P, out);
        else
            nms_coords_spec<19200, 32, false><<<blocks, 256>>>(coords, P, out);
    } else if ((HW % 256 == 0) && (M >= 10) && (M <= 255)) {
        const int blocks = total / 256;
        if (aligned16)
            nms_coords_fast<true><<<blocks, 256>>>(coords, P, out, HW, M);
        else
            nms_coords_fast<false><<<blocks, 256>>>(coords, P, out, HW, M);
    } else {
        const int blocks = (total + 255) / 256;
        nms_coords_kernel_generic<<<blocks, 256>>>(coords, P, out, HW, M, total);
    }
}

// round 17
// speedup vs baseline: 1.1364x; 1.1364x over previous
#include <cuda_runtime.h>
#include <stdint.h>

// Fused projection + greedy per-pixel NMS. Output dtype is FLOAT32.
//   coords_grid: [N, M, 3, H, W] f32,  anchor_P: [N, 3, 4] f32
//   out: [N, H, W, 8] f32 (indices as floats)
//
// R17: exact R15 body (proven 14.8us; R16's unrolled specialization spilled
// and is reverted), retiled to 128-thread CTAs at 16 blocks/SM. Same 2048
// thr/SM residency, but grid 2400/2368 resident shrinks the straggler tail
// (was 16 full-size CTAs beyond 1184 resident; now 32 half-size CTAs) and
// work-steals the early-exit drain at finer granularity.
#define TOPK 8

__device__ __forceinline__ float fast_rcp(float z) {
    float r;
    asm("rcp.approx.ftz.f32 %0, %1;" : "=f"(r) : "f"(z));
    return r;
}

#define PROJECT(cx, cy, cz, X, Y)                                             \
  do {                                                                        \
    const float X0 = fmaf(p00, (cx), fmaf(p01, (cy), fmaf(p02, (cz), p03)));  \
    const float X1 = fmaf(p10, (cx), fmaf(p11, (cy), fmaf(p12, (cz), p13)));  \
    const float X2 = fmaf(p20, (cx), fmaf(p21, (cy), fmaf(p22, (cz), p23)));  \
    const float zc = fmaxf(X2, 1e-6f);                                        \
    const float iv = fast_rcp(zc);                                            \
    (X) = X0 * iv;                                                            \
    (Y) = X1 * iv;                                                            \
  } while (0)

#define SUPPRESS_INSERT(MVAL)                                                 \
  do {                                                                        \
    float d2_[TOPK];                                                          \
    _Pragma("unroll")                                                         \
    for (int k = 0; k < TOPK; k++) {                                          \
      const float dx = sx[k] - x1;                                            \
      const float dy = sy[k] - y1;                                            \
      d2_[k] = fmaf(dx, dx, dy * dy);                                         \
    }                                                                         \
    const float dmn = fminf(fminf(fminf(d2_[0], d2_[1]), fminf(d2_[2], d2_[3])), \
                            fminf(fminf(d2_[4], d2_[5]), fminf(d2_[6], d2_[7]))); \
    if ((dmn > 4.0f) && (cnt < TOPK)) {                                       \
      _Pragma("unroll")                                                       \
      for (int k = 1; k < TOPK; k++) {                                        \
        if (cnt == k) { sx[k] = x1; sy[k] = y1; }                             \
      }                                                                       \
      si64 |= (uint64_t)(uint32_t)(MVAL) << (cnt * 8);                        \
      cnt++;                                                                  \
    }                                                                         \
  } while (0)

#define CAND_BODY(MVAL)                                                       \
  do {                                                                        \
    const float nx = pf[0];                                                   \
    const float ny = pf[plane];                                               \
    const float nz = pf[2 * plane];                                           \
    float x2, y2;                                                             \
    PROJECT(cx1, cy1, cz1, x2, y2);                                           \
    SUPPRESS_INSERT(MVAL);                                                    \
    x1 = x2; y1 = y2;                                                         \
    cx1 = nx; cy1 = ny; cz1 = nz;                                             \
    pf += mstride;                                                            \
  } while (0)

// Fast path: HW % 128 == 0 (CTA lies in one image), 10 <= M <= 255.
// 128 threads/CTA, 16 CTAs/SM (32-reg class) -> 2048 thr/SM.
template <bool VEC_STORE>
__global__ __launch_bounds__(128, 16)
void nms_coords_fast(const float* __restrict__ coords,
                     const float* __restrict__ P,
                     float* __restrict__ out,
                     int HW, int M)
{
    // Block-uniform image index -> uniform-register promotion.
    const int bpix = blockIdx.x * 128;
    const int n    = bpix / HW;
    const int pix  = bpix - n * HW + threadIdx.x;

    const float* Pn = P + n * 12;
    const float p00 = Pn[0], p01 = Pn[1], p02 = Pn[2],  p03 = Pn[3];
    const float p10 = Pn[4], p11 = Pn[5], p12 = Pn[6],  p13 = Pn[7];
    const float p20 = Pn[8], p21 = Pn[9], p22 = Pn[10], p23 = Pn[11];

    const long long plane   = HW;
    const long long mstride = 3 * plane;
    const float* base = coords + (long long)n * M * mstride + pix;

    float sx[TOPK], sy[TOPK];
#pragma unroll
    for (int k = 0; k < TOPK; k++) { sx[k] = 1e9f; sy[k] = 1e9f; }
    uint64_t si64 = 0;                    // 8 kept indices, byte-packed (M<256)

    // Peel m = 0: always kept; index byte stays 0.
    {
        const float cx = base[0];
        const float cy = base[plane];
        const float cz = base[2 * plane];
        PROJECT(cx, cy, cz, sx[0], sy[0]);
    }
    int cnt = 1;

    // Pipeline prime (M >= 10: indices 1..3 valid, no clamps).
    float x1, y1;
    {
        const float* s1 = base + mstride;
        const float cx = s1[0], cy = s1[plane], cz = s1[2 * plane];
        PROJECT(cx, cy, cz, x1, y1);
    }
    float cx1, cy1, cz1;
    {
        const float* s2 = base + 2 * mstride;
        cx1 = s2[0]; cy1 = s2[plane]; cz1 = s2[2 * plane];
    }
    const float* pf = base + 3 * mstride;

    // Vote-free warm-up m = 1..7 (cnt can't reach 8 yet; m+2 <= 9 <= M-1).
#pragma unroll
    for (int m = 1; m < TOPK; m++) { CAND_BODY(m); }

    // Checked region with prefetch: m = 8 .. M-3.
    bool alldone = false;
    for (int m = TOPK; m <= M - 3; m++) {
        CAND_BODY(m);
        if (__all_sync(0xffffffffu, cnt >= TOPK)) { alldone = true; break; }
    }

    // No-load epilogue for m = M-2, M-1 (skipped when early exit fired).
    if (!alldone) {
        {
            float x2, y2;
            PROJECT(cx1, cy1, cz1, x2, y2);
            SUPPRESS_INSERT(M - 2);
            x1 = x2; y1 = y2;
        }
        SUPPRESS_INSERT(M - 1);
    }

    // Unpack byte-packed indices to floats.
    const uint32_t lo = (uint32_t)si64;
    const uint32_t hi = (uint32_t)(si64 >> 32);
    const float f0 = (float)( lo        & 0xff);
    const float f1 = (float)((lo >>  8) & 0xff);
    const float f2 = (float)((lo >> 16) & 0xff);
    const float f3 = (float)((lo >> 24)       );
    const float f4 = (float)( hi        & 0xff);
    const float f5 = (float)((hi >>  8) & 0xff);
    const float f6 = (float)((hi >> 16) & 0xff);
    const float f7 = (float)((hi >> 24)       );

    const long long opix = (long long)n * HW + pix;
    if (VEC_STORE) {
        float4* o = reinterpret_cast<float4*>(out) + opix * 2;
        o[0] = make_float4(f0, f1, f2, f3);
        o[1] = make_float4(f4, f5, f6, f7);
    } else {
        float* o = out + opix * TOPK;
        o[0]=f0; o[1]=f1; o[2]=f2; o[3]=f3; o[4]=f4; o[5]=f5; o[6]=f6; o[7]=f7;
    }
}

// Generic fallback (any M >= 1, any HW alignment): simple, correct.
__global__ __launch_bounds__(256)
void nms_coords_kernel_generic(const float* __restrict__ coords,
                               const float* __restrict__ P,
                               float* __restrict__ out,
                               int HW, int M, int total)
{
    const int tid = blockIdx.x * 256 + threadIdx.x;
    if (tid >= total) return;
    const int n   = tid / HW;
    const int pix = tid - n * HW;
    const float* Pn = P + n * 12;
    const float p00 = Pn[0], p01 = Pn[1], p02 = Pn[2],  p03 = Pn[3];
    const float p10 = Pn[4], p11 = Pn[5], p12 = Pn[6],  p13 = Pn[7];
    const float p20 = Pn[8], p21 = Pn[9], p22 = Pn[10], p23 = Pn[11];
    const long long plane = HW, mstride = 3 * plane;
    const float* cm = coords + (long long)n * M * mstride + pix;

    float sx[TOPK], sy[TOPK]; int si[TOPK];
#pragma unroll
    for (int k = 0; k < TOPK; k++) { sx[k] = 1e9f; sy[k] = 1e9f; si[k] = 0; }
    int cnt = 0;
    for (int m = 0; m < M; m++, cm += mstride) {
        const float cx = cm[0], cy = cm[plane], cz = cm[2 * plane];
        const float X0 = fmaf(p00, cx, fmaf(p01, cy, fmaf(p02, cz, p03)));
        const float X1 = fmaf(p10, cx, fmaf(p11, cy, fmaf(p12, cz, p13)));
        const float X2 = fmaf(p20, cx, fmaf(p21, cy, fmaf(p22, cz, p23)));
        const float zc = fmaxf(X2, 1e-6f);
        const float x = X0 / zc, y = X1 / zc;
        float dmin = 3.402823e38f;
#pragma unroll
        for (int k = 0; k < TOPK; k++) {
            const float dx = sx[k] - x, dy = sy[k] - y;
            dmin = fminf(dmin, fmaf(dx, dx, dy * dy));
        }
        if (dmin > 4.0f && cnt < TOPK) {
#pragma unroll
            for (int k = 0; k < TOPK; k++)
                if (cnt == k) { sx[k] = x; sy[k] = y; si[k] = m; }
            cnt++;
        }
    }
    float* o = out + (long long)tid * TOPK;
#pragma unroll
    for (int k = 0; k < TOPK; k++) o[k] = (float)si[k];
}

extern "C" void kernel_launch(void* const* d_in, const int* in_sizes, int n_in,
                              void* d_out, int out_size)
{
    int ci = 0, pi = 0;
    for (int i = 1; i < n_in; i++) {
        if (in_sizes[i] > in_sizes[ci]) ci = i;
        if (in_sizes[i] < in_sizes[pi]) pi = i;
    }
    const float* coords = (const float*)d_in[ci];
    const float* P      = (const float*)d_in[pi];
    float* out          = (float*)d_out;

    const long long p_elems      = in_sizes[pi];
    const long long coords_elems = in_sizes[ci];
    const int N  = (int)(p_elems / 12);
    const int HW = (int)(out_size / (TOPK * (long long)N));
    const int M  = (int)(coords_elems / (3LL * N * HW));
    const int total = N * HW;

    const bool fast = (HW % 128 == 0) && (M >= 10) && (M <= 255);
    if (fast) {
        const int blocks = total / 128;            // exact
        if ((((uintptr_t)d_out) & 15u) == 0)
            nms_coords_fast<true><<<blocks, 128>>>(coords, P, out, HW, M);
        else
            nms_coords_fast<false><<<blocks, 128>>>(coords, P, out, HW, M);
    } else {
        const int blocks = (total + 255) / 256;
        nms_coords_kernel_generic<<<blocks, 256>>>(coords, P, out, HW, M, total);
    }
}